// round 16
// baseline (speedup 1.0000x reference)
#include <cuda_runtime.h>
#include <math.h>
#include <stdint.h>

#define B_DIM 8
#define S_DIM 2048
#define D_MODEL 512
#define D_K 64
#define EPSV 1e-6f

// Scratch for projected q (pre-scaled by dk^-0.5), k, v — stored TF32-ROUNDED
__device__ float g_q[B_DIM * S_DIM * D_K];
__device__ float g_k[B_DIM * S_DIM * D_K];
__device__ float g_v[B_DIM * S_DIM * D_K];

// ---------------- tf32 MMA helpers ----------------
__device__ __forceinline__ unsigned f2tf32(float f) {
    unsigned r;
    asm("cvt.rna.tf32.f32 %0, %1;" : "=r"(r) : "f"(f));
    return r;
}
__device__ __forceinline__ void mma_tf32(float* d, const unsigned* a, const unsigned* b) {
    asm volatile(
        "mma.sync.aligned.m16n8k8.row.col.f32.tf32.tf32.f32 "
        "{%0,%1,%2,%3}, {%4,%5,%6,%7}, {%8,%9}, {%0,%1,%2,%3};"
        : "+f"(d[0]), "+f"(d[1]), "+f"(d[2]), "+f"(d[3])
        : "r"(a[0]), "r"(a[1]), "r"(a[2]), "r"(a[3]), "r"(b[0]), "r"(b[1]));
}
#define CP16(dst_u32, src_ptr) \
    asm volatile("cp.async.ca.shared.global [%0], [%1], 16;" :: "r"(dst_u32), "l"(src_ptr))
#define CPCOMMIT() asm volatile("cp.async.commit_group;")
#define CPWAIT0()  asm volatile("cp.async.wait_group 0;")
#define CPWAIT1()  asm volatile("cp.async.wait_group 1;")

// ---------------------------------------------------------------------------
// Projection via tf32 MMA. Block: 128 rows x 64 cols (384 blocks -> better
// wave balance + multi-CTA occupancy). 256 thr = 8 warps; warp = 16 rows.
// K chunks of 16, cp.async double-buffered. smem: Xs[2][128][20], Ws[2][64][20]
// ---------------------------------------------------------------------------
#define PJ_XST 20
#define PJ_XBUF (128 * PJ_XST)
#define PJ_WBUF (64 * PJ_XST)

__global__ __launch_bounds__(256) void proj_mma_kernel(
    const float* __restrict__ Xq, const float* __restrict__ Xk, const float* __restrict__ Xv,
    const float* __restrict__ Wq, const float* __restrict__ bq,
    const float* __restrict__ Wk, const float* __restrict__ bk,
    const float* __restrict__ Wv, const float* __restrict__ bv)
{
    const float* X; const float* W; const float* bias; float* Out; float scale;
    if (blockIdx.y == 0)      { X = Xq; W = Wq; bias = bq; Out = g_q; scale = 0.125f; }
    else if (blockIdx.y == 1) { X = Xk; W = Wk; bias = bk; Out = g_k; scale = 1.0f; }
    else                      { X = Xv; W = Wv; bias = bv; Out = g_v; scale = 1.0f; }

    extern __shared__ float psh[];
    float* Xs = psh;                       // [2][128][20]
    float* Ws = psh + 2 * PJ_XBUF;         // [2][64][20]

    const int tid  = threadIdx.x;
    const int w    = tid >> 5;
    const int lane = tid & 31;
    const int g    = lane >> 2;
    const int tig  = lane & 3;
    const int r0   = blockIdx.x * 128;

    const uint32_t xs_u32 = (uint32_t)__cvta_generic_to_shared(Xs);
    const uint32_t ws_u32 = (uint32_t)__cvta_generic_to_shared(Ws);

    const int xl_r   = tid >> 1;          // 0..127
    const int xl_off = (tid & 1) * 8;     // 0 or 8 floats
    const int wl_n  = tid >> 2;           // 0..63
    const int wl_k4 = (tid & 3) * 4;      // 0,4,8,12

    float acc[8][4];
#pragma unroll
    for (int nt = 0; nt < 8; nt++)
#pragma unroll
        for (int e = 0; e < 4; e++) acc[nt][e] = 0.0f;

    // Prologue: chunk 0
#pragma unroll
    for (int h = 0; h < 2; h++)
        CP16(xs_u32 + (uint32_t)(xl_r * PJ_XST + xl_off + h * 4) * 4,
             X + (size_t)(r0 + xl_r) * D_MODEL + xl_off + h * 4);
    CP16(ws_u32 + (uint32_t)(wl_n * PJ_XST + wl_k4) * 4,
         W + (size_t)wl_n * D_MODEL + wl_k4);
    CPCOMMIT();

    const int NCH = D_MODEL / 16;   // 32
    for (int c = 0; c < NCH; c++) {
        if (c + 1 < NCH) {
            int k0 = (c + 1) * 16;
            uint32_t xb = xs_u32 + (uint32_t)(((c + 1) & 1) * PJ_XBUF) * 4;
            uint32_t wbb = ws_u32 + (uint32_t)(((c + 1) & 1) * PJ_WBUF) * 4;
#pragma unroll
            for (int h = 0; h < 2; h++)
                CP16(xb + (uint32_t)(xl_r * PJ_XST + xl_off + h * 4) * 4,
                     X + (size_t)(r0 + xl_r) * D_MODEL + k0 + xl_off + h * 4);
            CP16(wbb + (uint32_t)(wl_n * PJ_XST + wl_k4) * 4,
                 W + (size_t)wl_n * D_MODEL + k0 + wl_k4);
            CPCOMMIT();
            CPWAIT1();
        } else {
            CPWAIT0();
        }
        __syncthreads();

        const float* xb = Xs + (c & 1) * PJ_XBUF;
        const float* wb = Ws + (c & 1) * PJ_WBUF;
#pragma unroll
        for (int ks = 0; ks < 2; ks++) {
            const int kk = ks * 8;
            unsigned af[4];
            int rb = w * 16 + g;
            af[0] = f2tf32(xb[rb * PJ_XST + kk + tig]);
            af[1] = f2tf32(xb[(rb + 8) * PJ_XST + kk + tig]);
            af[2] = f2tf32(xb[rb * PJ_XST + kk + tig + 4]);
            af[3] = f2tf32(xb[(rb + 8) * PJ_XST + kk + tig + 4]);
#pragma unroll
            for (int nt = 0; nt < 8; nt++) {
                unsigned bf[2];
                bf[0] = f2tf32(wb[(nt * 8 + g) * PJ_XST + kk + tig]);
                bf[1] = f2tf32(wb[(nt * 8 + g) * PJ_XST + kk + tig + 4]);
                mma_tf32(acc[nt], af, bf);
            }
        }
        __syncthreads();
    }

    // Epilogue: (acc + bias) * scale, tf32-round, float2 stores
#pragma unroll
    for (int nt = 0; nt < 8; nt++) {
        int d = nt * 8 + tig * 2;
        float b0 = __ldg(bias + d), b1 = __ldg(bias + d + 1);
        int i = r0 + w * 16 + g;
        float v0 = (acc[nt][0] + b0) * scale;
        float v1 = (acc[nt][1] + b1) * scale;
        float v2 = (acc[nt][2] + b0) * scale;
        float v3 = (acc[nt][3] + b1) * scale;
        *(float2*)(Out + (size_t)i * D_K + d) =
            make_float2(__uint_as_float(f2tf32(v0)), __uint_as_float(f2tf32(v1)));
        *(float2*)(Out + (size_t)(i + 8) * D_K + d) =
            make_float2(__uint_as_float(f2tf32(v2)), __uint_as_float(f2tf32(v3)));
    }
}

// ---------------------------------------------------------------------------
// QK^T (tf32 MMA) + mask + softmax. Block = (batch, 16 q rows) x 2048 cols,
// 512 thr = 16 warps; warp w owns cols [w*128, +128).
// K staged in 3-buffer ring kt[3][2048][8] with 16B XOR swizzle
// (p = h ^ ((j>>2)&1)) -> cp.async 16B-aligned AND conflict-free A-frag LDS.
// ONE barrier per chunk (wait -> barrier -> issue c+2 -> compute).
// Mask + (qk==0) handling applied in the softmax phase with coalesced int4.
// smem: kt 3*16384 fl (sc[16][2052] aliases), qs[16][68] at +49152. 200960 B.
// ---------------------------------------------------------------------------
#define QK_BUF 16384   // 2048*8 floats per ring buffer

__global__ __launch_bounds__(512, 1) void qk_softmax_kernel(
    const int* __restrict__ amask, float* __restrict__ out_w)
{
    extern __shared__ float sh[];
    float* kt = sh;               // [3][2048][8] swizzled
    float* sc = sh;               // [16][2052] alias (used after compute)
    float* qs = sh + 3 * QK_BUF;  // [16][68]

    const int b    = blockIdx.y;
    const int q0   = blockIdx.x * 16;
    const int tid  = threadIdx.x;
    const int w    = tid >> 5;
    const int lane = tid & 31;
    const int g    = lane >> 2;
    const int tig  = lane & 3;

    // Stage q tile (16 x 64) into qs, stride 68
    {
        int r  = tid & 15;
        int kk = (tid >> 4) * 2;
        const float* qsrc = g_q + ((size_t)b * S_DIM + q0 + r) * D_K + kk;
        qs[r * 68 + kk]     = qsrc[0];
        qs[r * 68 + kk + 1] = qsrc[1];
    }

    const float* kb = g_k + (size_t)b * S_DIM * D_K;
    const uint32_t kt_u32 = (uint32_t)__cvta_generic_to_shared(kt);
    const int jrow = tid >> 1;          // 0..255
    const int lh   = tid & 1;           // 16B half

    float acc[8][2][4];
#pragma unroll
    for (int jt = 0; jt < 8; jt++)
#pragma unroll
        for (int it = 0; it < 2; it++)
#pragma unroll
            for (int e = 0; e < 4; e++) acc[jt][it][e] = 0.0f;

    // Loader: chunk c into ring buffer bi.  8 j-rows per thread, swizzled dst.
#define QK_LOAD(c_, bi_) do {                                                  \
        uint32_t base_ = kt_u32 + (uint32_t)((bi_) * QK_BUF) * 4;              \
        _Pragma("unroll")                                                      \
        for (int ii = 0; ii < 8; ii++) {                                       \
            int j_ = jrow + 256 * ii;                                          \
            int p_ = lh ^ ((j_ >> 2) & 1);                                     \
            CP16(base_ + (uint32_t)(j_ * 8 + p_ * 4) * 4,                      \
                 kb + (size_t)j_ * D_K + (c_) * 8 + lh * 4);                   \
        }                                                                      \
        CPCOMMIT();                                                            \
    } while (0)

    QK_LOAD(0, 0);
    QK_LOAD(1, 1);

    for (int c = 0; c < 8; c++) {
        if (c + 1 < 8) { CPWAIT1(); } else { CPWAIT0(); }
        __syncthreads();                       // chunk c visible; c-1 reads done
        if (c + 2 < 8) QK_LOAD(c + 2, (c + 2) % 3);

        // B fragments (q, pre-rounded -> raw bits)
        unsigned bf[2][2];
#pragma unroll
        for (int it = 0; it < 2; it++) {
            bf[it][0] = __float_as_uint(qs[(it * 8 + g) * 68 + c * 8 + tig]);
            bf[it][1] = __float_as_uint(qs[(it * 8 + g) * 68 + c * 8 + tig + 4]);
        }

        const float* kbuf = kt + (c % 3) * QK_BUF;
#pragma unroll
        for (int jt = 0; jt < 8; jt++) {
            int jr = w * 128 + jt * 16 + g;
            int sw = (jr >> 2) & 1;            // swizzle bit (same for jr, jr+8)
            unsigned af[4];
            af[0] = __float_as_uint(kbuf[jr * 8 + sw * 4 + tig]);
            af[1] = __float_as_uint(kbuf[(jr + 8) * 8 + sw * 4 + tig]);
            af[2] = __float_as_uint(kbuf[jr * 8 + (sw ^ 1) * 4 + tig]);
            af[3] = __float_as_uint(kbuf[(jr + 8) * 8 + (sw ^ 1) * 4 + tig]);
            mma_tf32(acc[jt][0], af, bf[0]);
            mma_tf32(acc[jt][1], af, bf[1]);
        }
    }
    __syncthreads();   // all compute done before sc overwrites kt region

    // Scatter raw scores into sc[i][j] (stride 2052; mask applied later)
#pragma unroll
    for (int jt = 0; jt < 8; jt++) {
        int j0 = w * 128 + jt * 16 + g;
#pragma unroll
        for (int it = 0; it < 2; it++) {
            int i0 = it * 8 + tig * 2;
#pragma unroll
            for (int e = 0; e < 4; e++) {
                int i = i0 + (e & 1);
                int j = j0 + (e >= 2 ? 8 : 0);
                sc[i * 2052 + j] = acc[jt][it][e];
            }
        }
    }
    __syncthreads();

    // Softmax: warp w handles row w. Coalesced mask int4 + eps subst here.
    {
        const float* row  = sc + w * 2052;
        const int*   mrow = amask + ((size_t)b * S_DIM + q0 + w) * S_DIM;
        float4 x[16];
        float mx = -3.402823466e38f;
#pragma unroll
        for (int it = 0; it < 16; it++) {
            x[it] = *(const float4*)(row + (lane + 32 * it) * 4);
            int4 m = *(const int4*)(mrow + (lane + 32 * it) * 4);
            if (x[it].x == 0.0f || m.x == 0) x[it].x = EPSV;
            if (x[it].y == 0.0f || m.y == 0) x[it].y = EPSV;
            if (x[it].z == 0.0f || m.z == 0) x[it].z = EPSV;
            if (x[it].w == 0.0f || m.w == 0) x[it].w = EPSV;
            mx = fmaxf(mx, fmaxf(fmaxf(x[it].x, x[it].y), fmaxf(x[it].z, x[it].w)));
        }
#pragma unroll
        for (int o = 16; o; o >>= 1) mx = fmaxf(mx, __shfl_xor_sync(0xffffffffu, mx, o));

        float sum = 0.0f;
#pragma unroll
        for (int it = 0; it < 16; it++) {
            x[it].x = __expf(x[it].x - mx);
            x[it].y = __expf(x[it].y - mx);
            x[it].z = __expf(x[it].z - mx);
            x[it].w = __expf(x[it].w - mx);
            sum += x[it].x + x[it].y + x[it].z + x[it].w;
        }
#pragma unroll
        for (int o = 16; o; o >>= 1) sum += __shfl_xor_sync(0xffffffffu, sum, o);
        const float inv = 1.0f / sum;

        float* wr = out_w + ((size_t)b * S_DIM + q0 + w) * S_DIM;
#pragma unroll
        for (int it = 0; it < 16; it++) {
            *(float4*)(wr + (lane + 32 * it) * 4) =
                make_float4(x[it].x * inv, x[it].y * inv, x[it].z * inv, x[it].w * inv);
        }
    }
#undef QK_LOAD
}

// ---------------------------------------------------------------------------
// PV (tf32 MMA): 3-stage cp.async ring, one barrier per chunk, 3 CTAs/SM.
// Block = 64 rows x 64 cols, 128 thr = 4 warps. pt[3][64][36], vt[3][32][72].
// ---------------------------------------------------------------------------
#define PV_PBUF (64 * 36)
#define PV_VBUF (32 * 72)

__global__ __launch_bounds__(128, 3) void pv_kernel(
    const float* __restrict__ out_w, float* __restrict__ out_attn)
{
    extern __shared__ float pvsh[];
    float* pt = pvsh;                   // [3][64][36]
    float* vt = pvsh + 3 * PV_PBUF;     // [3][32][72]

    const int b    = blockIdx.y;
    const int r0   = blockIdx.x * 64;
    const int tid  = threadIdx.x;
    const int w    = tid >> 5;
    const int lane = tid & 31;
    const int g    = lane >> 2;
    const int tig  = lane & 3;

    const float* wb = out_w + ((size_t)b * S_DIM + r0) * S_DIM;
    const float* vb = g_v + (size_t)b * S_DIM * D_K;
    const uint32_t pt_u32 = (uint32_t)__cvta_generic_to_shared(pt);
    const uint32_t vt_u32 = (uint32_t)__cvta_generic_to_shared(vt);

    const int p_i   = tid >> 1;
    const int p_off = (tid & 1) * 16;
    const int v_j   = tid >> 2;
    const int v_f4  = tid & 3;

    float acc[8][4];
#pragma unroll
    for (int nt = 0; nt < 8; nt++)
#pragma unroll
        for (int e = 0; e < 4; e++) acc[nt][e] = 0.0f;

#define PV_LOAD(c_, bi_) do {                                                  \
        uint32_t pb_ = pt_u32 + (uint32_t)((bi_) * PV_PBUF) * 4;               \
        uint32_t vb_ = vt_u32 + (uint32_t)((bi_) * PV_VBUF) * 4;               \
        int j0_ = (c_) * 32;                                                   \
        _Pragma("unroll")                                                      \
        for (int k = 0; k < 4; k++)                                            \
            CP16(pb_ + (uint32_t)(p_i * 36 + p_off + k * 4) * 4,               \
                 wb + (size_t)p_i * S_DIM + j0_ + p_off + k * 4);              \
        _Pragma("unroll")                                                      \
        for (int k = 0; k < 4; k++)                                            \
            CP16(vb_ + (uint32_t)(v_j * 72 + (v_f4 + 4 * k) * 4) * 4,          \
                 vb + (size_t)(j0_ + v_j) * D_K + (v_f4 + 4 * k) * 4);         \
        CPCOMMIT();                                                            \
    } while (0)

    PV_LOAD(0, 0);
    PV_LOAD(1, 1);

    const int NCH = S_DIM / 32;   // 64
    for (int c = 0; c < NCH; c++) {
        if (c + 1 < NCH) { CPWAIT1(); } else { CPWAIT0(); }
        __syncthreads();
        if (c + 2 < NCH) PV_LOAD(c + 2, (c + 2) % 3);

        const float* pb = pt + (c % 3) * PV_PBUF;
        const float* vv = vt + (c % 3) * PV_VBUF;
        const int ir = w * 16 + g;
#pragma unroll
        for (int ks = 0; ks < 4; ks++) {
            unsigned af[4];
            af[0] = __float_as_uint(pb[ir * 36 + ks * 8 + tig]);
            af[1] = __float_as_uint(pb[(ir + 8) * 36 + ks * 8 + tig]);
            af[2] = __float_as_uint(pb[ir * 36 + ks * 8 + tig + 4]);
            af[3] = __float_as_uint(pb[(ir + 8) * 36 + ks * 8 + tig + 4]);
#pragma unroll
            for (int nt = 0; nt < 8; nt++) {
                unsigned bf[2];
                bf[0] = __float_as_uint(vv[(ks * 8 + tig) * 72 + nt * 8 + g]);
                bf[1] = __float_as_uint(vv[(ks * 8 + tig + 4) * 72 + nt * 8 + g]);
                mma_tf32(acc[nt], af, bf);
            }
        }
    }

    float* ob = out_attn + ((size_t)b * S_DIM + r0) * D_K;
#pragma unroll
    for (int nt = 0; nt < 8; nt++) {
        int d = nt * 8 + tig * 2;
        int i = w * 16 + g;
        *(float2*)(ob + (size_t)i * D_K + d)       = make_float2(acc[nt][0], acc[nt][1]);
        *(float2*)(ob + (size_t)(i + 8) * D_K + d) = make_float2(acc[nt][2], acc[nt][3]);
    }
#undef PV_LOAD
}

// ---------------------------------------------------------------------------
extern "C" void kernel_launch(void* const* d_in, const int* in_sizes, int n_in,
                              void* d_out, int out_size)
{
    const float* query = (const float*)d_in[0];
    const float* key   = (const float*)d_in[1];
    const float* value = (const float*)d_in[2];
    const int*   amask = (const int*)d_in[3];
    const float* Wq = (const float*)d_in[4];
    const float* bq = (const float*)d_in[5];
    const float* Wk = (const float*)d_in[6];
    const float* bk = (const float*)d_in[7];
    const float* Wv = (const float*)d_in[8];
    const float* bv = (const float*)d_in[9];

    float* out_attn = (float*)d_out;                                // (B,S,64)
    float* out_w    = (float*)d_out + (size_t)B_DIM * S_DIM * D_K;  // (B,S,S)

    const size_t psmem = (size_t)(2 * PJ_XBUF + 2 * PJ_WBUF) * sizeof(float);  // 30720 B
    cudaFuncSetAttribute(proj_mma_kernel,
                         cudaFuncAttributeMaxDynamicSharedMemorySize, (int)psmem);
    proj_mma_kernel<<<dim3((B_DIM * S_DIM) / 128, 3), 256, psmem>>>(
        query, value /*placeholder fixed below*/ == value ? key : key, value,
        Wq, bq, Wk, bk, Wv, bv);
    // NOTE: the ternary above is a no-op guard against accidental arg swap;
    // it always passes `key` as the second argument.

    const size_t qsmem = (size_t)(3 * QK_BUF + 16 * 68) * sizeof(float);  // 200960 B
    cudaFuncSetAttribute(qk_softmax_kernel,
                         cudaFuncAttributeMaxDynamicSharedMemorySize, (int)qsmem);
    qk_softmax_kernel<<<dim3(S_DIM / 16, B_DIM), 512, qsmem>>>(amask, out_w);

    const size_t pvsmem = (size_t)(3 * PV_PBUF + 3 * PV_VBUF) * sizeof(float);  // 55296 B
    cudaFuncSetAttribute(pv_kernel,
                         cudaFuncAttributeMaxDynamicSharedMemorySize, (int)pvsmem);
    pv_kernel<<<dim3(S_DIM / 64, B_DIM), 128, pvsmem>>>(out_w, out_attn);
}

// round 17
// speedup vs baseline: 1.0058x; 1.0058x over previous
#include <cuda_runtime.h>
#include <math.h>
#include <stdint.h>

#define B_DIM 8
#define S_DIM 2048
#define D_MODEL 512
#define D_K 64
#define EPSV 1e-6f

// Scratch for projected q (pre-scaled by dk^-0.5), k, v — stored TF32-ROUNDED
__device__ float g_q[B_DIM * S_DIM * D_K];
__device__ float g_k[B_DIM * S_DIM * D_K];
__device__ float g_v[B_DIM * S_DIM * D_K];

// ---------------- tf32 MMA helpers ----------------
__device__ __forceinline__ unsigned f2tf32(float f) {
    unsigned r;
    asm("cvt.rna.tf32.f32 %0, %1;" : "=r"(r) : "f"(f));
    return r;
}
__device__ __forceinline__ void mma_tf32(float* d, const unsigned* a, const unsigned* b) {
    asm volatile(
        "mma.sync.aligned.m16n8k8.row.col.f32.tf32.tf32.f32 "
        "{%0,%1,%2,%3}, {%4,%5,%6,%7}, {%8,%9}, {%0,%1,%2,%3};"
        : "+f"(d[0]), "+f"(d[1]), "+f"(d[2]), "+f"(d[3])
        : "r"(a[0]), "r"(a[1]), "r"(a[2]), "r"(a[3]), "r"(b[0]), "r"(b[1]));
}
#define CP16(dst_u32, src_ptr) \
    asm volatile("cp.async.ca.shared.global [%0], [%1], 16;" :: "r"(dst_u32), "l"(src_ptr))
#define CPCOMMIT() asm volatile("cp.async.commit_group;")
#define CPWAIT0()  asm volatile("cp.async.wait_group 0;")
#define CPWAIT1()  asm volatile("cp.async.wait_group 1;")

// ---------------------------------------------------------------------------
// Projection via tf32 MMA. Block: 128 rows x 64 cols (384 blocks -> better
// wave balance + multi-CTA occupancy). 256 thr = 8 warps; warp = 16 rows.
// K chunks of 16, cp.async double-buffered. smem: Xs[2][128][20], Ws[2][64][20]
// ---------------------------------------------------------------------------
#define PJ_XST 20
#define PJ_XBUF (128 * PJ_XST)
#define PJ_WBUF (64 * PJ_XST)

__global__ __launch_bounds__(256) void proj_mma_kernel(
    const float* __restrict__ Xq, const float* __restrict__ Xk, const float* __restrict__ Xv,
    const float* __restrict__ Wq, const float* __restrict__ bq,
    const float* __restrict__ Wk, const float* __restrict__ bk,
    const float* __restrict__ Wv, const float* __restrict__ bv)
{
    const float* X; const float* W; const float* bias; float* Out; float scale;
    if (blockIdx.y == 0)      { X = Xq; W = Wq; bias = bq; Out = g_q; scale = 0.125f; }
    else if (blockIdx.y == 1) { X = Xk; W = Wk; bias = bk; Out = g_k; scale = 1.0f; }
    else                      { X = Xv; W = Wv; bias = bv; Out = g_v; scale = 1.0f; }

    extern __shared__ float psh[];
    float* Xs = psh;                       // [2][128][20]
    float* Ws = psh + 2 * PJ_XBUF;         // [2][64][20]

    const int tid  = threadIdx.x;
    const int w    = tid >> 5;
    const int lane = tid & 31;
    const int g    = lane >> 2;
    const int tig  = lane & 3;
    const int r0   = blockIdx.x * 128;

    const uint32_t xs_u32 = (uint32_t)__cvta_generic_to_shared(Xs);
    const uint32_t ws_u32 = (uint32_t)__cvta_generic_to_shared(Ws);

    const int xl_r   = tid >> 1;          // 0..127
    const int xl_off = (tid & 1) * 8;     // 0 or 8 floats
    const int wl_n  = tid >> 2;           // 0..63
    const int wl_k4 = (tid & 3) * 4;      // 0,4,8,12

    float acc[8][4];
#pragma unroll
    for (int nt = 0; nt < 8; nt++)
#pragma unroll
        for (int e = 0; e < 4; e++) acc[nt][e] = 0.0f;

    // Prologue: chunk 0
#pragma unroll
    for (int h = 0; h < 2; h++)
        CP16(xs_u32 + (uint32_t)(xl_r * PJ_XST + xl_off + h * 4) * 4,
             X + (size_t)(r0 + xl_r) * D_MODEL + xl_off + h * 4);
    CP16(ws_u32 + (uint32_t)(wl_n * PJ_XST + wl_k4) * 4,
         W + (size_t)wl_n * D_MODEL + wl_k4);
    CPCOMMIT();

    const int NCH = D_MODEL / 16;   // 32
    for (int c = 0; c < NCH; c++) {
        if (c + 1 < NCH) {
            int k0 = (c + 1) * 16;
            uint32_t xb = xs_u32 + (uint32_t)(((c + 1) & 1) * PJ_XBUF) * 4;
            uint32_t wbb = ws_u32 + (uint32_t)(((c + 1) & 1) * PJ_WBUF) * 4;
#pragma unroll
            for (int h = 0; h < 2; h++)
                CP16(xb + (uint32_t)(xl_r * PJ_XST + xl_off + h * 4) * 4,
                     X + (size_t)(r0 + xl_r) * D_MODEL + k0 + xl_off + h * 4);
            CP16(wbb + (uint32_t)(wl_n * PJ_XST + wl_k4) * 4,
                 W + (size_t)wl_n * D_MODEL + k0 + wl_k4);
            CPCOMMIT();
            CPWAIT1();
        } else {
            CPWAIT0();
        }
        __syncthreads();

        const float* xb = Xs + (c & 1) * PJ_XBUF;
        const float* wb = Ws + (c & 1) * PJ_WBUF;
#pragma unroll
        for (int ks = 0; ks < 2; ks++) {
            const int kk = ks * 8;
            unsigned af[4];
            int rb = w * 16 + g;
            af[0] = f2tf32(xb[rb * PJ_XST + kk + tig]);
            af[1] = f2tf32(xb[(rb + 8) * PJ_XST + kk + tig]);
            af[2] = f2tf32(xb[rb * PJ_XST + kk + tig + 4]);
            af[3] = f2tf32(xb[(rb + 8) * PJ_XST + kk + tig + 4]);
#pragma unroll
            for (int nt = 0; nt < 8; nt++) {
                unsigned bf[2];
                bf[0] = f2tf32(wb[(nt * 8 + g) * PJ_XST + kk + tig]);
                bf[1] = f2tf32(wb[(nt * 8 + g) * PJ_XST + kk + tig + 4]);
                mma_tf32(acc[nt], af, bf);
            }
        }
        __syncthreads();
    }

    // Epilogue: (acc + bias) * scale, tf32-round, float2 stores
#pragma unroll
    for (int nt = 0; nt < 8; nt++) {
        int d = nt * 8 + tig * 2;
        float b0 = __ldg(bias + d), b1 = __ldg(bias + d + 1);
        int i = r0 + w * 16 + g;
        float v0 = (acc[nt][0] + b0) * scale;
        float v1 = (acc[nt][1] + b1) * scale;
        float v2 = (acc[nt][2] + b0) * scale;
        float v3 = (acc[nt][3] + b1) * scale;
        *(float2*)(Out + (size_t)i * D_K + d) =
            make_float2(__uint_as_float(f2tf32(v0)), __uint_as_float(f2tf32(v1)));
        *(float2*)(Out + (size_t)(i + 8) * D_K + d) =
            make_float2(__uint_as_float(f2tf32(v2)), __uint_as_float(f2tf32(v3)));
    }
}

// ---------------------------------------------------------------------------
// QK^T (tf32 MMA) + mask + softmax. Block = (batch, 16 q rows) x 2048 cols,
// 512 thr = 16 warps; warp w owns cols [w*128, +128).
// K staged in 3-buffer ring kt[3][2048][8] with 16B XOR swizzle
// (p = h ^ ((j>>2)&1)) -> cp.async 16B-aligned AND conflict-free A-frag LDS.
// ONE barrier per chunk (wait -> barrier -> issue c+2 -> compute).
// Mask + (qk==0) handling applied in the softmax phase with coalesced int4.
// smem: kt 3*16384 fl (sc[16][2052] aliases), qs[16][68] at +49152. 200960 B.
// ---------------------------------------------------------------------------
#define QK_BUF 16384   // 2048*8 floats per ring buffer

__global__ __launch_bounds__(512, 1) void qk_softmax_kernel(
    const int* __restrict__ amask, float* __restrict__ out_w)
{
    extern __shared__ float sh[];
    float* kt = sh;               // [3][2048][8] swizzled
    float* sc = sh;               // [16][2052] alias (used after compute)
    float* qs = sh + 3 * QK_BUF;  // [16][68]

    const int b    = blockIdx.y;
    const int q0   = blockIdx.x * 16;
    const int tid  = threadIdx.x;
    const int w    = tid >> 5;
    const int lane = tid & 31;
    const int g    = lane >> 2;
    const int tig  = lane & 3;

    // Stage q tile (16 x 64) into qs, stride 68
    {
        int r  = tid & 15;
        int kk = (tid >> 4) * 2;
        const float* qsrc = g_q + ((size_t)b * S_DIM + q0 + r) * D_K + kk;
        qs[r * 68 + kk]     = qsrc[0];
        qs[r * 68 + kk + 1] = qsrc[1];
    }

    const float* kb = g_k + (size_t)b * S_DIM * D_K;
    const uint32_t kt_u32 = (uint32_t)__cvta_generic_to_shared(kt);
    const int jrow = tid >> 1;          // 0..255
    const int lh   = tid & 1;           // 16B half

    float acc[8][2][4];
#pragma unroll
    for (int jt = 0; jt < 8; jt++)
#pragma unroll
        for (int it = 0; it < 2; it++)
#pragma unroll
            for (int e = 0; e < 4; e++) acc[jt][it][e] = 0.0f;

    // Loader: chunk c into ring buffer bi.  8 j-rows per thread, swizzled dst.
#define QK_LOAD(c_, bi_) do {                                                  \
        uint32_t base_ = kt_u32 + (uint32_t)((bi_) * QK_BUF) * 4;              \
        _Pragma("unroll")                                                      \
        for (int ii = 0; ii < 8; ii++) {                                       \
            int j_ = jrow + 256 * ii;                                          \
            int p_ = lh ^ ((j_ >> 2) & 1);                                     \
            CP16(base_ + (uint32_t)(j_ * 8 + p_ * 4) * 4,                      \
                 kb + (size_t)j_ * D_K + (c_) * 8 + lh * 4);                   \
        }                                                                      \
        CPCOMMIT();                                                            \
    } while (0)

    QK_LOAD(0, 0);
    QK_LOAD(1, 1);

    for (int c = 0; c < 8; c++) {
        if (c + 1 < 8) { CPWAIT1(); } else { CPWAIT0(); }
        __syncthreads();                       // chunk c visible; c-1 reads done
        if (c + 2 < 8) QK_LOAD(c + 2, (c + 2) % 3);

        // B fragments (q, pre-rounded -> raw bits)
        unsigned bf[2][2];
#pragma unroll
        for (int it = 0; it < 2; it++) {
            bf[it][0] = __float_as_uint(qs[(it * 8 + g) * 68 + c * 8 + tig]);
            bf[it][1] = __float_as_uint(qs[(it * 8 + g) * 68 + c * 8 + tig + 4]);
        }

        const float* kbuf = kt + (c % 3) * QK_BUF;
#pragma unroll
        for (int jt = 0; jt < 8; jt++) {
            int jr = w * 128 + jt * 16 + g;
            int sw = (jr >> 2) & 1;            // swizzle bit (same for jr, jr+8)
            unsigned af[4];
            af[0] = __float_as_uint(kbuf[jr * 8 + sw * 4 + tig]);
            af[1] = __float_as_uint(kbuf[(jr + 8) * 8 + sw * 4 + tig]);
            af[2] = __float_as_uint(kbuf[jr * 8 + (sw ^ 1) * 4 + tig]);
            af[3] = __float_as_uint(kbuf[(jr + 8) * 8 + (sw ^ 1) * 4 + tig]);
            mma_tf32(acc[jt][0], af, bf[0]);
            mma_tf32(acc[jt][1], af, bf[1]);
        }
    }
    __syncthreads();   // all compute done before sc overwrites kt region

    // Scatter raw scores into sc[i][j] (stride 2052; mask applied later)
#pragma unroll
    for (int jt = 0; jt < 8; jt++) {
        int j0 = w * 128 + jt * 16 + g;
#pragma unroll
        for (int it = 0; it < 2; it++) {
            int i0 = it * 8 + tig * 2;
#pragma unroll
            for (int e = 0; e < 4; e++) {
                int i = i0 + (e & 1);
                int j = j0 + (e >= 2 ? 8 : 0);
                sc[i * 2052 + j] = acc[jt][it][e];
            }
        }
    }
    __syncthreads();

    // Softmax: warp w handles row w. Coalesced mask int4 + eps subst here.
    {
        const float* row  = sc + w * 2052;
        const int*   mrow = amask + ((size_t)b * S_DIM + q0 + w) * S_DIM;
        float4 x[16];
        float mx = -3.402823466e38f;
#pragma unroll
        for (int it = 0; it < 16; it++) {
            x[it] = *(const float4*)(row + (lane + 32 * it) * 4);
            int4 m = *(const int4*)(mrow + (lane + 32 * it) * 4);
            if (x[it].x == 0.0f || m.x == 0) x[it].x = EPSV;
            if (x[it].y == 0.0f || m.y == 0) x[it].y = EPSV;
            if (x[it].z == 0.0f || m.z == 0) x[it].z = EPSV;
            if (x[it].w == 0.0f || m.w == 0) x[it].w = EPSV;
            mx = fmaxf(mx, fmaxf(fmaxf(x[it].x, x[it].y), fmaxf(x[it].z, x[it].w)));
        }
#pragma unroll
        for (int o = 16; o; o >>= 1) mx = fmaxf(mx, __shfl_xor_sync(0xffffffffu, mx, o));

        float sum = 0.0f;
#pragma unroll
        for (int it = 0; it < 16; it++) {
            x[it].x = __expf(x[it].x - mx);
            x[it].y = __expf(x[it].y - mx);
            x[it].z = __expf(x[it].z - mx);
            x[it].w = __expf(x[it].w - mx);
            sum += x[it].x + x[it].y + x[it].z + x[it].w;
        }
#pragma unroll
        for (int o = 16; o; o >>= 1) sum += __shfl_xor_sync(0xffffffffu, sum, o);
        const float inv = 1.0f / sum;

        float* wr = out_w + ((size_t)b * S_DIM + q0 + w) * S_DIM;
#pragma unroll
        for (int it = 0; it < 16; it++) {
            *(float4*)(wr + (lane + 32 * it) * 4) =
                make_float4(x[it].x * inv, x[it].y * inv, x[it].z * inv, x[it].w * inv);
        }
    }
#undef QK_LOAD
}

// ---------------------------------------------------------------------------
// PV (tf32 MMA): 3-stage cp.async ring, one barrier per chunk, 3 CTAs/SM.
// Block = 64 rows x 64 cols, 128 thr = 4 warps. pt[3][64][36], vt[3][32][72].
// ---------------------------------------------------------------------------
#define PV_PBUF (64 * 36)
#define PV_VBUF (32 * 72)

__global__ __launch_bounds__(128, 3) void pv_kernel(
    const float* __restrict__ out_w, float* __restrict__ out_attn)
{
    extern __shared__ float pvsh[];
    float* pt = pvsh;                   // [3][64][36]
    float* vt = pvsh + 3 * PV_PBUF;     // [3][32][72]

    const int b    = blockIdx.y;
    const int r0   = blockIdx.x * 64;
    const int tid  = threadIdx.x;
    const int w    = tid >> 5;
    const int lane = tid & 31;
    const int g    = lane >> 2;
    const int tig  = lane & 3;

    const float* wb = out_w + ((size_t)b * S_DIM + r0) * S_DIM;
    const float* vb = g_v + (size_t)b * S_DIM * D_K;
    const uint32_t pt_u32 = (uint32_t)__cvta_generic_to_shared(pt);
    const uint32_t vt_u32 = (uint32_t)__cvta_generic_to_shared(vt);

    const int p_i   = tid >> 1;
    const int p_off = (tid & 1) * 16;
    const int v_j   = tid >> 2;
    const int v_f4  = tid & 3;

    float acc[8][4];
#pragma unroll
    for (int nt = 0; nt < 8; nt++)
#pragma unroll
        for (int e = 0; e < 4; e++) acc[nt][e] = 0.0f;

#define PV_LOAD(c_, bi_) do {                                                  \
        uint32_t pb_ = pt_u32 + (uint32_t)((bi_) * PV_PBUF) * 4;               \
        uint32_t vb_ = vt_u32 + (uint32_t)((bi_) * PV_VBUF) * 4;               \
        int j0_ = (c_) * 32;                                                   \
        _Pragma("unroll")                                                      \
        for (int k = 0; k < 4; k++)                                            \
            CP16(pb_ + (uint32_t)(p_i * 36 + p_off + k * 4) * 4,               \
                 wb + (size_t)p_i * S_DIM + j0_ + p_off + k * 4);              \
        _Pragma("unroll")                                                      \
        for (int k = 0; k < 4; k++)                                            \
            CP16(vb_ + (uint32_t)(v_j * 72 + (v_f4 + 4 * k) * 4) * 4,          \
                 vb + (size_t)(j0_ + v_j) * D_K + (v_f4 + 4 * k) * 4);         \
        CPCOMMIT();                                                            \
    } while (0)

    PV_LOAD(0, 0);
    PV_LOAD(1, 1);

    const int NCH = S_DIM / 32;   // 64
    for (int c = 0; c < NCH; c++) {
        if (c + 1 < NCH) { CPWAIT1(); } else { CPWAIT0(); }
        __syncthreads();
        if (c + 2 < NCH) PV_LOAD(c + 2, (c + 2) % 3);

        const float* pb = pt + (c % 3) * PV_PBUF;
        const float* vv = vt + (c % 3) * PV_VBUF;
        const int ir = w * 16 + g;
#pragma unroll
        for (int ks = 0; ks < 4; ks++) {
            unsigned af[4];
            af[0] = __float_as_uint(pb[ir * 36 + ks * 8 + tig]);
            af[1] = __float_as_uint(pb[(ir + 8) * 36 + ks * 8 + tig]);
            af[2] = __float_as_uint(pb[ir * 36 + ks * 8 + tig + 4]);
            af[3] = __float_as_uint(pb[(ir + 8) * 36 + ks * 8 + tig + 4]);
#pragma unroll
            for (int nt = 0; nt < 8; nt++) {
                unsigned bf[2];
                bf[0] = __float_as_uint(vv[(ks * 8 + tig) * 72 + nt * 8 + g]);
                bf[1] = __float_as_uint(vv[(ks * 8 + tig + 4) * 72 + nt * 8 + g]);
                mma_tf32(acc[nt], af, bf);
            }
        }
    }

    float* ob = out_attn + ((size_t)b * S_DIM + r0) * D_K;
#pragma unroll
    for (int nt = 0; nt < 8; nt++) {
        int d = nt * 8 + tig * 2;
        int i = w * 16 + g;
        *(float2*)(ob + (size_t)i * D_K + d)       = make_float2(acc[nt][0], acc[nt][1]);
        *(float2*)(ob + (size_t)(i + 8) * D_K + d) = make_float2(acc[nt][2], acc[nt][3]);
    }
#undef PV_LOAD
}

// ---------------------------------------------------------------------------
extern "C" void kernel_launch(void* const* d_in, const int* in_sizes, int n_in,
                              void* d_out, int out_size)
{
    const float* query = (const float*)d_in[0];
    const float* key   = (const float*)d_in[1];
    const float* value = (const float*)d_in[2];
    const int*   amask = (const int*)d_in[3];
    const float* Wq = (const float*)d_in[4];
    const float* bq = (const float*)d_in[5];
    const float* Wk = (const float*)d_in[6];
    const float* bk = (const float*)d_in[7];
    const float* Wv = (const float*)d_in[8];
    const float* bv = (const float*)d_in[9];

    float* out_attn = (float*)d_out;                                // (B,S,64)
    float* out_w    = (float*)d_out + (size_t)B_DIM * S_DIM * D_K;  // (B,S,S)

    const size_t psmem = (size_t)(2 * PJ_XBUF + 2 * PJ_WBUF) * sizeof(float);  // 30720 B
    cudaFuncSetAttribute(proj_mma_kernel,
                         cudaFuncAttributeMaxDynamicSharedMemorySize, (int)psmem);
    proj_mma_kernel<<<dim3((B_DIM * S_DIM) / 128, 3), 256, psmem>>>(
        query, value /*placeholder fixed below*/ == value ? key : key, value,
        Wq, bq, Wk, bk, Wv, bv);
    // NOTE: the ternary above is a no-op guard against accidental arg swap;
    // it always passes `key` as the second argument.

    const size_t qsmem = (size_t)(3 * QK_BUF + 16 * 68) * sizeof(float);  // 200960 B
    cudaFuncSetAttribute(qk_softmax_kernel,
                         cudaFuncAttributeMaxDynamicSharedMemorySize, (int)qsmem);
    qk_softmax_kernel<<<dim3(S_DIM / 16, B_DIM), 512, qsmem>>>(amask, out_w);

    const size_t pvsmem = (size_t)(3 * PV_PBUF + 3 * PV_VBUF) * sizeof(float);  // 55296 B
    cudaFuncSetAttribute(pv_kernel,
                         cudaFuncAttributeMaxDynamicSharedMemorySize, (int)pvsmem);
    pv_kernel<<<dim3(S_DIM / 64, B_DIM), 128, pvsmem>>>(out_w, out_attn);
}